// round 16
// baseline (speedup 1.0000x reference)
#include <cuda_runtime.h>
#include <stdint.h>

// Inputs (metadata order):
//  0: vertex_dofs  [V,1]  f32
//  1: edge_dofs    [E,2]  f32
//  2: face_dofs    [C,1]  f32
//  3: y            [C,10,16] f32
//  4: faces        [C,3]  i32
//  5: faces_to_edges [C,3] i32
//  6: edge_orientation [C,3] i32
// Output: [C,16] f32

#define NB 10
#define QPTS 16
#define THREADS 32      // single-warp blocks: proven-best granularity
#define PF_DIST 8192    // cells of L2 prefetch lookahead (~5 MB, ~1000 blocks)

__global__ __launch_bounds__(THREADS)
void quadfn_kernel(const float* __restrict__ vertex_dofs,
                   const float* __restrict__ edge_dofs,
                   const float* __restrict__ face_dofs,
                   const float* __restrict__ y,
                   const int*   __restrict__ faces,
                   const int*   __restrict__ f2e,
                   const int*   __restrict__ orient,
                   float*       __restrict__ out,
                   int C)
{
    const int tid  = blockIdx.x * THREADS + threadIdx.x;
    const int c    = tid >> 2;          // one cell per 4-lane group
    const int lane = threadIdx.x & 31;
    const int qg   = lane & 3;          // which float4 of Q=16
    const int grp  = lane & ~3;         // group base lane within warp

    if (c >= C) return;                 // tail: whole 4-lane groups drop out

    // ---- Phase -1: L2 prefetch for a block ~1000 launches ahead.
    // Zero register cost; keeps a pure linear DRAM read stream running
    // decoupled from any consumer. When that block runs (~1 us later,
    // >> DRAM latency), its y LDGs hit L2 instead of eating the full
    // ~600-cycle DRAM latency at block start. 5 MB lookahead << 126 MB L2.
    {
        const int cp = c + PF_DIST;
        if (cp < C) {
            const char* pf = (const char*)(y + (size_t)cp * NB * QPTS);
            // 5 x 128B lines per cell: lanes 0-3 take lines 0-3, lane 0 line 4
            asm volatile("prefetch.global.L2 [%0];" :: "l"(pf + qg * 128));
            if (qg == 0)
                asm volatile("prefetch.global.L2 [%0];" :: "l"(pf + 512));
        }
    }

    // ---- Phase 0: streaming y tile (measured-fastest ordering).
    // 10 independent LDG.128 in flight across the gather chain.
    // __ldcs = evict-first: y has zero reuse; keep L2 for the dof tables.
    float4 v[NB];
    {
        const float4* yv = reinterpret_cast<const float4*>(
                               y + (size_t)c * NB * QPTS) + qg;
        #pragma unroll
        for (int b = 0; b < NB; b++)
            v[b] = __ldcs(yv + b * (QPTS / 4));
    }

    // ---- Phase 1: cooperative gather within the 4-lane group (no smem,
    // no __syncthreads — warps stay fully independent).
    float wv = 0.f, wa = 0.f, wb = 0.f, wf = 0.f;
    if (qg < 3) {
        int vidx = __ldg(&faces[3 * c + qg]);
        wv = __ldg(&vertex_dofs[vidx]);
        int    eidx = __ldg(&f2e[3 * c + qg]);
        int    o    = __ldg(&orient[3 * c + qg]);
        float2 ed   = __ldg((const float2*)edge_dofs + eidx);
        wa = (o != 0) ? ed.x : ed.y;   // first edge dof
        wb = (o != 0) ? ed.y : ed.x;   // second edge dof
    } else {
        wf = __ldg(&face_dofs[c]);
    }

    // ---- Phase 2: broadcast the 10 weights across the group via shuffle.
    const unsigned m = 0xffffffffu;
    float w0 = __shfl_sync(m, wv, grp + 0);
    float w1 = __shfl_sync(m, wv, grp + 1);
    float w2 = __shfl_sync(m, wv, grp + 2);
    float w3 = __shfl_sync(m, wa, grp + 0);
    float w4 = __shfl_sync(m, wb, grp + 0);
    float w5 = __shfl_sync(m, wa, grp + 1);
    float w6 = __shfl_sync(m, wb, grp + 1);
    float w7 = __shfl_sync(m, wa, grp + 2);
    float w8 = __shfl_sync(m, wb, grp + 2);
    float w9 = __shfl_sync(m, wf, grp + 3);

    // ---- Phase 3: contraction on the prefetched registers ----
    float4 acc;
    acc.x = w0 * v[0].x; acc.y = w0 * v[0].y;
    acc.z = w0 * v[0].z; acc.w = w0 * v[0].w;

    #define ACC(W, B)                         \
        acc.x = fmaf(W, v[B].x, acc.x);       \
        acc.y = fmaf(W, v[B].y, acc.y);       \
        acc.z = fmaf(W, v[B].z, acc.z);       \
        acc.w = fmaf(W, v[B].w, acc.w);
    ACC(w1, 1) ACC(w2, 2) ACC(w3, 3) ACC(w4, 4)
    ACC(w5, 5) ACC(w6, 6) ACC(w7, 7) ACC(w8, 8) ACC(w9, 9)
    #undef ACC

    __stcs(reinterpret_cast<float4*>(out + (size_t)c * QPTS) + qg, acc);
}

extern "C" void kernel_launch(void* const* d_in, const int* in_sizes, int n_in,
                              void* d_out, int out_size)
{
    const float* vertex_dofs = (const float*)d_in[0];
    const float* edge_dofs   = (const float*)d_in[1];
    const float* face_dofs   = (const float*)d_in[2];
    const float* y           = (const float*)d_in[3];
    const int*   faces       = (const int*)d_in[4];
    const int*   f2e         = (const int*)d_in[5];
    const int*   orient      = (const int*)d_in[6];
    float*       out         = (float*)d_out;

    // Derive C from y: [C, NB, Q]
    int C = in_sizes[3] / (NB * QPTS);

    long long total_threads = (long long)C * 4;
    int blocks = (int)((total_threads + THREADS - 1) / THREADS);
    quadfn_kernel<<<blocks, THREADS>>>(vertex_dofs, edge_dofs, face_dofs, y,
                                       faces, f2e, orient, out, C);
}